// round 16
// baseline (speedup 1.0000x reference)
#include <cuda_runtime.h>
#include <math.h>

#define N_GAUSS 4096
#define IMG_H 128
#define IMG_W 128
#define N_SEG 16
#define BCAP  128                    // per-(tile,seg) bucket capacity
#define GRID  1024
#define BLK   128
#define ALPHA_MIN (1.0f/255.0f)
#define ALPHA_MAX 0.999f
#define EPS2D 0.3f

// ---------------- scratch (device globals; zero-initialized at load) ----------------
__device__ float2 d_mxy[N_GAUSS];                 // projected mean
__device__ float4 d_con[N_GAUSS];                 // 0.5*ca, cb, 0.5*cc, op
__device__ float4 d_col[N_GAUSS];                 // r, g, b, cutoff
// per-(tile,seg) buckets: entry = (z_bits<<12) | id ; u64 order == (z, id)
__device__ int                g_bcnt[64 * N_SEG]; // reset by tile's last CTA
__device__ unsigned long long g_bucket[64 * N_SEG * BCAP];
__device__ float4 g_seg[64 * N_SEG * 256];        // per (tile,seg,pixel) partials
__device__ int    g_tcnt[64];                     // per-tile combine counters (reset ph1)

// barrier state — monotonic counters, NEVER reset (epoch from g_release at entry)
__device__ unsigned g_grp[32];
__device__ unsigned g_root;
__device__ unsigned g_release;

__device__ __forceinline__ int z_seg(float z) {
    int s = (int)((z - 2.0f) * (16.0f / 6.0f));
    return min(N_SEG - 1, max(0, s));
}

__device__ __forceinline__ unsigned ld_acq(const unsigned* p) {
    unsigned v;
    asm volatile("ld.acquire.gpu.u32 %0, [%1];" : "=r"(v) : "l"(p) : "memory");
    return v;
}

__device__ __forceinline__ int atomicAddAcqRelGpu(int* p, int v) {
    int old;
    asm volatile("atom.acq_rel.gpu.add.s32 %0, [%1], %2;"
                 : "=r"(old) : "l"(p), "r"(v) : "memory");
    return old;
}

// Hierarchical grid barrier (R14-proven): 32 group counters -> root -> release.
__device__ __forceinline__ void grid_barrier(unsigned target) {
    __syncthreads();
    if (threadIdx.x == 0) {
        unsigned old;
        asm volatile("atom.release.gpu.add.u32 %0, [%1], 1;"
                     : "=r"(old) : "l"(&g_grp[blockIdx.x & 31]) : "memory");
        if ((old & 31u) == 31u) {
            unsigned ro;
            asm volatile("atom.acq_rel.gpu.add.u32 %0, [%1], 1;"
                         : "=r"(ro) : "l"(&g_root) : "memory");
            if ((ro & 31u) == 31u) {
                asm volatile("red.release.gpu.add.u32 [%0], 1;"
                             :: "l"(&g_release) : "memory");
            }
        }
        while ((int)(ld_acq(&g_release) - target) < 0)
            asm volatile("nanosleep.u32 128;");
    }
    __syncthreads();
}

__global__ void __launch_bounds__(BLK, 8) mega_kernel(
                            const float* __restrict__ Ks,
                            const float* __restrict__ vm,
                            const float* __restrict__ means,
                            const float* __restrict__ quats,
                            const float* __restrict__ scales,
                            const float* __restrict__ ops,
                            const float* __restrict__ rgb,
                            float* __restrict__ out)
{
    __shared__ unsigned long long szid[BCAP];
    __shared__ float2 smxy[BCAP];
    __shared__ float4 scon[BCAP];
    __shared__ float4 scol[BCAP];
    __shared__ int    sIsLast;

    const int b = blockIdx.x;
    const int t = threadIdx.x;

    unsigned r0 = 0;
    if (t == 0) r0 = ld_acq(&g_release);

    // ====== phase 1: prep + direct (tile,seg) binning (CTAs 0-31); CTA 32 resets ======
    if (b < 32) {
        int i = b * BLK + t;

        float mx0 = means[i*3+0], my0 = means[i*3+1], mz0 = means[i*3+2];
        float qw = quats[i*4+0], qx = quats[i*4+1], qy = quats[i*4+2], qz = quats[i*4+3];
        float s0 = scales[i*3+0], s1 = scales[i*3+1], s2 = scales[i*3+2];
        float op = ops[i];
        float cr = rgb[i*3+0], cg = rgb[i*3+1], cb2 = rgb[i*3+2];

        float R00 = vm[0],  R01 = vm[1],  R02 = vm[2],  T0 = vm[3];
        float R10 = vm[4],  R11 = vm[5],  R12 = vm[6],  T1 = vm[7];
        float R20 = vm[8],  R21 = vm[9],  R22 = vm[10], T2 = vm[11];

        float x = R00*mx0 + R01*my0 + R02*mz0 + T0;
        float y = R10*mx0 + R11*my0 + R12*mz0 + T1;
        float z = R20*mx0 + R21*my0 + R22*mz0 + T2;

        float zs = (fabsf(z) < 1e-6f) ? 1e-6f : z;
        float rz = __fdividef(1.0f, zs);

        float qn = rsqrtf(qw*qw + qx*qx + qy*qy + qz*qz);
        qw *= qn; qx *= qn; qy *= qn; qz *= qn;
        float r00 = 1.f - 2.f*(qy*qy + qz*qz), r01 = 2.f*(qx*qy - qw*qz), r02 = 2.f*(qx*qz + qw*qy);
        float r10 = 2.f*(qx*qy + qw*qz), r11 = 1.f - 2.f*(qx*qx + qz*qz), r12 = 2.f*(qy*qz - qw*qx);
        float r20 = 2.f*(qx*qz - qw*qy), r21 = 2.f*(qy*qz + qw*qx), r22 = 1.f - 2.f*(qx*qx + qy*qy);

        float m00 = r00*s0, m01 = r01*s1, m02 = r02*s2;
        float m10 = r10*s0, m11 = r11*s1, m12 = r12*s2;
        float m20 = r20*s0, m21 = r21*s1, m22 = r22*s2;

        float c00 = m00*m00 + m01*m01 + m02*m02;
        float c01 = m00*m10 + m01*m11 + m02*m12;
        float c02 = m00*m20 + m01*m21 + m02*m22;
        float c11 = m10*m10 + m11*m11 + m12*m12;
        float c12 = m10*m20 + m11*m21 + m12*m22;
        float c22 = m20*m20 + m21*m21 + m22*m22;

        float t00 = R00*c00 + R01*c01 + R02*c02;
        float t01 = R00*c01 + R01*c11 + R02*c12;
        float t02 = R00*c02 + R01*c12 + R02*c22;
        float t10 = R10*c00 + R11*c01 + R12*c02;
        float t11 = R10*c01 + R11*c11 + R12*c12;
        float t12 = R10*c02 + R11*c12 + R12*c22;
        float t20 = R20*c00 + R21*c01 + R22*c02;
        float t21 = R20*c01 + R21*c11 + R22*c12;
        float t22 = R20*c02 + R21*c12 + R22*c22;
        float cc00 = t00*R00 + t01*R01 + t02*R02;
        float cc01 = t00*R10 + t01*R11 + t02*R12;
        float cc02 = t00*R20 + t01*R21 + t02*R22;
        float cc11 = t10*R10 + t11*R11 + t12*R12;
        float cc12 = t10*R20 + t11*R21 + t12*R22;
        float cc22 = t20*R20 + t21*R21 + t22*R22;

        float fx = Ks[0], fy = Ks[4], cxK = Ks[2], cyK = Ks[5];
        float j00 = fx*rz, j02 = -fx*x*rz*rz;
        float j11 = fy*rz, j12 = -fy*y*rz*rz;

        float a2 = j00*j00*cc00 + 2.f*j00*j02*cc02 + j02*j02*cc22;
        float b2 = j00*(cc01*j11 + cc02*j12) + j02*(cc12*j11 + cc22*j12);
        float c2 = j11*j11*cc11 + 2.f*j11*j12*cc12 + j12*j12*cc22;

        float a = a2 + EPS2D;
        float c = c2 + EPS2D;
        float bb = b2;
        float det = a*c - bb*bb;
        bool valid = (z > 0.01f) && (z < 100.0f) && (det > 0.0f);
        float dets = (det > 0.0f) ? det : 1.0f;
        float rdet = __fdividef(1.0f, dets);
        float ica =  c * rdet;
        float icb = -bb * rdet;
        float icc =  a * rdet;

        float mpx = fx*x*rz + cxK;
        float mpy = fy*y*rz + cyK;
        float smax = __logf(255.0f * op);

        d_mxy[i] = make_float2(mpx, mpy);
        d_con[i] = make_float4(0.5f*ica, icb, 0.5f*icc, op);
        d_col[i] = make_float4(cr, cg, cb2, smax + 0.02f);

        if (valid && smax > 0.0f) {
            float inv = 2.0f * smax * dets;
            float rx = sqrtf(inv * icc) * 1.0001f + 0.01f;
            float ry = sqrtf(inv * ica) * 1.0001f + 0.01f;
            // exact ceil/floor forms of the interval tile tests
            const float inv16 = 1.0f / 16.0f;
            int tx_lo = max(0, (int)ceilf ((mpx - rx - 15.5f) * inv16));
            int tx_hi = min(7, (int)floorf((mpx + rx -  0.5f) * inv16));
            int ty_lo = max(0, (int)ceilf ((mpy - ry - 15.5f) * inv16));
            int ty_hi = min(7, (int)floorf((mpy + ry -  0.5f) * inv16));
            int seg = z_seg(z);
            unsigned long long entry =
                ((unsigned long long)__float_as_uint(z) << 12) | (unsigned)i;
            for (int ty = ty_lo; ty <= ty_hi; ty++)
                for (int tx = tx_lo; tx <= tx_hi; tx++) {
                    int bidx = (ty * 8 + tx) * N_SEG + seg;
                    int p = atomicAdd(&g_bcnt[bidx], 1);
                    if (p < BCAP) g_bucket[bidx * BCAP + p] = entry;
                }
        }
    } else if (b == 32) {
        // reset per-tile combine counters before any phase-2 increment
        if (t < 64) g_tcnt[t] = 0;
    }

    grid_barrier(r0 + 1);

    // ====== phase 2: render from bucket (tile, seg) + fused per-tile combine ======
    {
        const int tile = b >> 4, seg = b & 15;
        const int tx = tile & 7, ty = tile >> 3;
        const int lx = t & 15, ly = t >> 4;            // ly in 0..7
        const float px  = tx*16 + lx + 0.5f;
        const float py0 = ty*16 + ly + 0.5f;
        const float py1 = py0 + 8.0f;

        const int bidx = tile * N_SEG + seg;
        const int k = min(__ldcg(&g_bcnt[bidx]), BCAP);

        // load bucket entries (k <= 128 -> single pass)
        if (t < k) szid[t] = __ldcg(&g_bucket[bidx * BCAP + t]);
        __syncthreads();

        // exact (z, id) rank -> depth-ordered attribute gather
        if (t < k) {
            unsigned long long e = szid[t];
            int rank = 0;
            for (int j = 0; j < k; j++) rank += (szid[j] < e);
            int id = (int)(e & 0xFFFull);
            smxy[rank] = d_mxy[id];
            scon[rank] = d_con[id];
            scol[rank] = d_col[id];
        }
        __syncthreads();

        float T0 = 1.0f, Cr0 = 0.0f, Cg0 = 0.0f, Cb0 = 0.0f;
        float T1 = 1.0f, Cr1 = 0.0f, Cg1 = 0.0f, Cb1 = 0.0f;

        for (int i = 0; i < k; i++) {
            float2 mu = smxy[i];
            float4 co = scon[i];                  // (0.5a, b, 0.5c, op)
            float dx  = px - mu.x;
            float dy0 = py0 - mu.y;
            float dy1 = py1 - mu.y;
            float sig0 = fmaf(co.x, dx*dx, fmaf(co.z, dy0*dy0, co.y*(dx*dy0)));
            float sig1 = fmaf(co.x, dx*dx, fmaf(co.z, dy1*dy1, co.y*(dx*dy1)));
            float4 col = scol[i];                 // (r, g, b, cutoff)
            bool pre = ((sig0 >= 0.0f) && (sig0 <= col.w))
                    || ((sig1 >= 0.0f) && (sig1 <= col.w));
            if (__any_sync(0xffffffffu, pre)) {
                float al0 = fminf(co.w * __expf(-sig0), ALPHA_MAX);
                float al1 = fminf(co.w * __expf(-sig1), ALPHA_MAX);
                float w0 = ((sig0 >= 0.0f) && (al0 >= ALPHA_MIN)) ? al0 * T0 : 0.0f;
                float w1 = ((sig1 >= 0.0f) && (al1 >= ALPHA_MIN)) ? al1 * T1 : 0.0f;
                Cr0 = fmaf(w0, col.x, Cr0); Cr1 = fmaf(w1, col.x, Cr1);
                Cg0 = fmaf(w0, col.y, Cg0); Cg1 = fmaf(w1, col.y, Cg1);
                Cb0 = fmaf(w0, col.z, Cb0); Cb1 = fmaf(w1, col.z, Cb1);
                T0 -= w0;                    T1 -= w1;
            }
        }

        float4* segp = &g_seg[bidx * 256];
        __stcg(segp + (ly * 16 + lx),       make_float4(Cr0, Cg0, Cb0, T0));
        __stcg(segp + ((ly + 8) * 16 + lx), make_float4(Cr1, Cg1, Cb1, T1));

        // fused combine: last CTA of this tile (R7/R15-proven acq_rel pattern)
        __syncthreads();
        if (t == 0)
            sIsLast = (atomicAddAcqRelGpu(&g_tcnt[tile], 1) == N_SEG - 1) ? 1 : 0;
        __syncthreads();

        if (sIsLast) {
            // reset this tile's 16 bucket counters for the next call
            if (t < N_SEG) g_bcnt[tile * N_SEG + t] = 0;

            const float4* basep = &g_seg[tile * N_SEG * 256];
            #pragma unroll
            for (int pxn = 0; pxn < 2; pxn++) {
                int tin = (ly + pxn * 8) * 16 + lx;
                float aCr = 0.0f, aCg = 0.0f, aCb = 0.0f, aT = 1.0f;
                #pragma unroll
                for (int s = 0; s < N_SEG; s++) {
                    float4 p = __ldcg(basep + s * 256 + tin);
                    aCr = fmaf(aT, p.x, aCr);
                    aCg = fmaf(aT, p.y, aCg);
                    aCb = fmaf(aT, p.z, aCb);
                    aT *= p.w;
                }
                int x = tx*16 + lx, y = ty*16 + ly + pxn*8;
                int ppos = y * IMG_W + x;
                out[ppos]                 = aCr;
                out[IMG_H*IMG_W + ppos]   = aCg;
                out[2*IMG_H*IMG_W + ppos] = aCb;
            }
        }
    }
}

// ---------------- launch ----------------
extern "C" void kernel_launch(void* const* d_in, const int* in_sizes, int n_in,
                              void* d_out, int out_size)
{
    const float* Ks     = (const float*)d_in[0];
    const float* vm     = (const float*)d_in[1];
    const float* means  = (const float*)d_in[2];
    const float* quats  = (const float*)d_in[3];
    const float* scales = (const float*)d_in[4];
    const float* ops    = (const float*)d_in[5];
    const float* rgb    = (const float*)d_in[6];
    float* out = (float*)d_out;

    mega_kernel<<<GRID, BLK>>>(Ks, vm, means, quats, scales, ops, rgb, out);
}

// round 17
// speedup vs baseline: 1.1216x; 1.1216x over previous
#include <cuda_runtime.h>
#include <math.h>

#define N_GAUSS 4096
#define IMG_H 128
#define IMG_W 128
#define N_SEG 16
#define N_ROW 8
#define BCAP  160                    // per-(row,seg) list capacity
#define SCAP  160                    // per-(tile,seg) survivor capacity
#define GRID  1024
#define BLK   128
#define ALPHA_MIN (1.0f/255.0f)
#define ALPHA_MAX 0.999f
#define EPS2D 0.3f

// ---------------- scratch (device globals; zero-initialized at load) ----------------
__device__ float2 d_mxy[N_GAUSS];                 // projected mean
__device__ float4 d_con[N_GAUSS];                 // 0.5*ca, cb, 0.5*cc, op
__device__ float4 d_col[N_GAUSS];                 // r, g, b, cutoff
// per-(row,seg) lists: entry = (z_bits<<24)|(bbox<<12)|id ; u64 order == (z,bbox,id)
__device__ int                g_bcnt[N_ROW * N_SEG];   // reset by row's last tile
__device__ unsigned long long g_bucket[N_ROW * N_SEG * BCAP];
__device__ float4 g_seg[64 * N_SEG * 256];        // per (tile,seg,pixel) partials
__device__ int    g_tcnt[64];                     // per-tile combine counters (reset ph1)
__device__ int    g_rcnt[N_ROW];                  // per-row completion (self-reset)

// barrier state — monotonic counters, NEVER reset (epoch from g_release at entry)
__device__ unsigned g_grp[32];
__device__ unsigned g_root;
__device__ unsigned g_release;

__device__ __forceinline__ int z_seg(float z) {
    int s = (int)((z - 2.0f) * (16.0f / 6.0f));
    return min(N_SEG - 1, max(0, s));
}

__device__ __forceinline__ unsigned ld_acq(const unsigned* p) {
    unsigned v;
    asm volatile("ld.acquire.gpu.u32 %0, [%1];" : "=r"(v) : "l"(p) : "memory");
    return v;
}

__device__ __forceinline__ int atomicAddAcqRelGpu(int* p, int v) {
    int old;
    asm volatile("atom.acq_rel.gpu.add.s32 %0, [%1], %2;"
                 : "=r"(old) : "l"(p), "r"(v) : "memory");
    return old;
}

// Hierarchical grid barrier (R14-proven): 32 group counters -> root -> release.
__device__ __forceinline__ void grid_barrier(unsigned target) {
    __syncthreads();
    if (threadIdx.x == 0) {
        unsigned old;
        asm volatile("atom.release.gpu.add.u32 %0, [%1], 1;"
                     : "=r"(old) : "l"(&g_grp[blockIdx.x & 31]) : "memory");
        if ((old & 31u) == 31u) {
            unsigned ro;
            asm volatile("atom.acq_rel.gpu.add.u32 %0, [%1], 1;"
                         : "=r"(ro) : "l"(&g_root) : "memory");
            if ((ro & 31u) == 31u) {
                asm volatile("red.release.gpu.add.u32 [%0], 1;"
                             :: "l"(&g_release) : "memory");
            }
        }
        while ((int)(ld_acq(&g_release) - target) < 0)
            asm volatile("nanosleep.u32 128;");
    }
    __syncthreads();
}

__global__ void __launch_bounds__(BLK, 8) mega_kernel(
                            const float* __restrict__ Ks,
                            const float* __restrict__ vm,
                            const float* __restrict__ means,
                            const float* __restrict__ quats,
                            const float* __restrict__ scales,
                            const float* __restrict__ ops,
                            const float* __restrict__ rgb,
                            float* __restrict__ out)
{
    __shared__ unsigned long long szid[SCAP];
    __shared__ float2 smxy[SCAP];
    __shared__ float4 scon[SCAP];
    __shared__ float4 scol[SCAP];
    __shared__ int    scnt;
    __shared__ int    sIsLast;

    const int b = blockIdx.x;
    const int t = threadIdx.x;

    unsigned r0 = 0;
    if (t == 0) r0 = ld_acq(&g_release);

    // ====== phase 1: prep + (row,seg) binning (CTAs 0-31); CTA 32 resets tcnt ======
    if (b < 32) {
        int i = b * BLK + t;

        float mx0 = means[i*3+0], my0 = means[i*3+1], mz0 = means[i*3+2];
        float qw = quats[i*4+0], qx = quats[i*4+1], qy = quats[i*4+2], qz = quats[i*4+3];
        float s0 = scales[i*3+0], s1 = scales[i*3+1], s2 = scales[i*3+2];
        float op = ops[i];
        float cr = rgb[i*3+0], cg = rgb[i*3+1], cb2 = rgb[i*3+2];

        float R00 = vm[0],  R01 = vm[1],  R02 = vm[2],  T0 = vm[3];
        float R10 = vm[4],  R11 = vm[5],  R12 = vm[6],  T1 = vm[7];
        float R20 = vm[8],  R21 = vm[9],  R22 = vm[10], T2 = vm[11];

        float x = R00*mx0 + R01*my0 + R02*mz0 + T0;
        float y = R10*mx0 + R11*my0 + R12*mz0 + T1;
        float z = R20*mx0 + R21*my0 + R22*mz0 + T2;

        float zs = (fabsf(z) < 1e-6f) ? 1e-6f : z;
        float rz = __fdividef(1.0f, zs);

        float qn = rsqrtf(qw*qw + qx*qx + qy*qy + qz*qz);
        qw *= qn; qx *= qn; qy *= qn; qz *= qn;
        float r00 = 1.f - 2.f*(qy*qy + qz*qz), r01 = 2.f*(qx*qy - qw*qz), r02 = 2.f*(qx*qz + qw*qy);
        float r10 = 2.f*(qx*qy + qw*qz), r11 = 1.f - 2.f*(qx*qx + qz*qz), r12 = 2.f*(qy*qz - qw*qx);
        float r20 = 2.f*(qx*qz - qw*qy), r21 = 2.f*(qy*qz + qw*qx), r22 = 1.f - 2.f*(qx*qx + qy*qy);

        float m00 = r00*s0, m01 = r01*s1, m02 = r02*s2;
        float m10 = r10*s0, m11 = r11*s1, m12 = r12*s2;
        float m20 = r20*s0, m21 = r21*s1, m22 = r22*s2;

        float c00 = m00*m00 + m01*m01 + m02*m02;
        float c01 = m00*m10 + m01*m11 + m02*m12;
        float c02 = m00*m20 + m01*m21 + m02*m22;
        float c11 = m10*m10 + m11*m11 + m12*m12;
        float c12 = m10*m20 + m11*m21 + m12*m22;
        float c22 = m20*m20 + m21*m21 + m22*m22;

        float t00 = R00*c00 + R01*c01 + R02*c02;
        float t01 = R00*c01 + R01*c11 + R02*c12;
        float t02 = R00*c02 + R01*c12 + R02*c22;
        float t10 = R10*c00 + R11*c01 + R12*c02;
        float t11 = R10*c01 + R11*c11 + R12*c12;
        float t12 = R10*c02 + R11*c12 + R12*c22;
        float t20 = R20*c00 + R21*c01 + R22*c02;
        float t21 = R20*c01 + R21*c11 + R22*c12;
        float t22 = R20*c02 + R21*c12 + R22*c22;
        float cc00 = t00*R00 + t01*R01 + t02*R02;
        float cc01 = t00*R10 + t01*R11 + t02*R12;
        float cc02 = t00*R20 + t01*R21 + t02*R22;
        float cc11 = t10*R10 + t11*R11 + t12*R12;
        float cc12 = t10*R20 + t11*R21 + t12*R22;
        float cc22 = t20*R20 + t21*R21 + t22*R22;

        float fx = Ks[0], fy = Ks[4], cxK = Ks[2], cyK = Ks[5];
        float j00 = fx*rz, j02 = -fx*x*rz*rz;
        float j11 = fy*rz, j12 = -fy*y*rz*rz;

        float a2 = j00*j00*cc00 + 2.f*j00*j02*cc02 + j02*j02*cc22;
        float b2 = j00*(cc01*j11 + cc02*j12) + j02*(cc12*j11 + cc22*j12);
        float c2 = j11*j11*cc11 + 2.f*j11*j12*cc12 + j12*j12*cc22;

        float a = a2 + EPS2D;
        float c = c2 + EPS2D;
        float bb = b2;
        float det = a*c - bb*bb;
        bool valid = (z > 0.01f) && (z < 100.0f) && (det > 0.0f);
        float dets = (det > 0.0f) ? det : 1.0f;
        float rdet = __fdividef(1.0f, dets);
        float ica =  c * rdet;
        float icb = -bb * rdet;
        float icc =  a * rdet;

        float mpx = fx*x*rz + cxK;
        float mpy = fy*y*rz + cyK;
        float smax = __logf(255.0f * op);

        d_mxy[i] = make_float2(mpx, mpy);
        d_con[i] = make_float4(0.5f*ica, icb, 0.5f*icc, op);
        d_col[i] = make_float4(cr, cg, cb2, smax + 0.02f);

        if (valid && smax > 0.0f) {
            float inv = 2.0f * smax * dets;
            float rx = sqrtf(inv * icc) * 1.0001f + 0.01f;
            float ry = sqrtf(inv * ica) * 1.0001f + 0.01f;
            // exact ceil/floor forms of the interval tile tests
            const float inv16 = 1.0f / 16.0f;
            int tx_lo = max(0, (int)ceilf ((mpx - rx - 15.5f) * inv16));
            int tx_hi = min(7, (int)floorf((mpx + rx -  0.5f) * inv16));
            int ty_lo = max(0, (int)ceilf ((mpy - ry - 15.5f) * inv16));
            int ty_hi = min(7, (int)floorf((mpy + ry -  0.5f) * inv16));
            if (tx_lo <= tx_hi && ty_lo <= ty_hi) {
                int seg = z_seg(z);
                unsigned bbox = (unsigned)((tx_lo << 9) | (tx_hi << 6) | (ty_lo << 3) | ty_hi);
                unsigned long long entry =
                      ((unsigned long long)__float_as_uint(z) << 24)
                    | ((unsigned long long)bbox << 12)
                    | (unsigned)i;
                // push to each spanned row list (~1-2 rows)
                for (int r = ty_lo; r <= ty_hi; r++) {
                    int bidx = r * N_SEG + seg;
                    int p = atomicAdd(&g_bcnt[bidx], 1);
                    if (p < BCAP) g_bucket[bidx * BCAP + p] = entry;
                }
            }
        }
    } else if (b == 32) {
        // reset per-tile combine counters before any phase-2 increment
        if (t < 64) g_tcnt[t] = 0;
    }

    grid_barrier(r0 + 1);

    // ====== phase 2: render (tile, seg) from row list + fused per-tile combine ======
    {
        const int tile = b >> 4, seg = b & 15;
        const int tx = tile & 7, ty = tile >> 3;
        const int lx = t & 15, ly = t >> 4;            // ly in 0..7
        const float px  = tx*16 + lx + 0.5f;
        const float py0 = ty*16 + ly + 0.5f;
        const float py1 = py0 + 8.0f;

        const int bidx = ty * N_SEG + seg;
        const int k = min(__ldcg(&g_bcnt[bidx]), BCAP);

        if (t == 0) scnt = 0;
        __syncthreads();

        // unordered cull (rank restores order) — no internal barriers
        for (int idx = t; idx < k; idx += BLK) {
            unsigned long long e = __ldcg(&g_bucket[bidx * BCAP + idx]);
            unsigned bbox = (unsigned)(e >> 12) & 0xFFFu;
            int txlo = (bbox >> 9) & 7, txhi = (bbox >> 6) & 7;
            if (tx >= txlo && tx <= txhi) {
                int pos = atomicAdd(&scnt, 1);
                if (pos < SCAP) szid[pos] = e;
            }
        }
        __syncthreads();
        const int sc = min(scnt, SCAP);

        // exact (z,bbox,id) rank among survivors -> depth-ordered attribute gather
        for (int i = t; i < sc; i += BLK) {
            unsigned long long e = szid[i];
            int rank = 0;
            for (int j = 0; j < sc; j++) rank += (szid[j] < e);
            int id = (int)(e & 0xFFFull);
            smxy[rank] = d_mxy[id];
            scon[rank] = d_con[id];
            scol[rank] = d_col[id];
        }
        __syncthreads();

        float T0 = 1.0f, Cr0 = 0.0f, Cg0 = 0.0f, Cb0 = 0.0f;
        float T1 = 1.0f, Cr1 = 0.0f, Cg1 = 0.0f, Cb1 = 0.0f;

        for (int i = 0; i < sc; i++) {
            float2 mu = smxy[i];
            float4 co = scon[i];                  // (0.5a, b, 0.5c, op)
            float dx  = px - mu.x;
            float dy0 = py0 - mu.y;
            float dy1 = py1 - mu.y;
            float sig0 = fmaf(co.x, dx*dx, fmaf(co.z, dy0*dy0, co.y*(dx*dy0)));
            float sig1 = fmaf(co.x, dx*dx, fmaf(co.z, dy1*dy1, co.y*(dx*dy1)));
            float4 col = scol[i];                 // (r, g, b, cutoff)
            bool pre = ((sig0 >= 0.0f) && (sig0 <= col.w))
                    || ((sig1 >= 0.0f) && (sig1 <= col.w));
            if (__any_sync(0xffffffffu, pre)) {
                float al0 = fminf(co.w * __expf(-sig0), ALPHA_MAX);
                float al1 = fminf(co.w * __expf(-sig1), ALPHA_MAX);
                float w0 = ((sig0 >= 0.0f) && (al0 >= ALPHA_MIN)) ? al0 * T0 : 0.0f;
                float w1 = ((sig1 >= 0.0f) && (al1 >= ALPHA_MIN)) ? al1 * T1 : 0.0f;
                Cr0 = fmaf(w0, col.x, Cr0); Cr1 = fmaf(w1, col.x, Cr1);
                Cg0 = fmaf(w0, col.y, Cg0); Cg1 = fmaf(w1, col.y, Cg1);
                Cb0 = fmaf(w0, col.z, Cb0); Cb1 = fmaf(w1, col.z, Cb1);
                T0 -= w0;                    T1 -= w1;
            }
        }

        float4* segp = &g_seg[(tile * N_SEG + seg) * 256];
        __stcg(segp + (ly * 16 + lx),       make_float4(Cr0, Cg0, Cb0, T0));
        __stcg(segp + ((ly + 8) * 16 + lx), make_float4(Cr1, Cg1, Cb1, T1));

        // fused combine: last CTA of this tile (R7/R15-proven acq_rel pattern)
        __syncthreads();
        if (t == 0)
            sIsLast = (atomicAddAcqRelGpu(&g_tcnt[tile], 1) == N_SEG - 1) ? 1 : 0;
        __syncthreads();

        if (sIsLast) {
            const float4* basep = &g_seg[tile * N_SEG * 256];
            #pragma unroll
            for (int pxn = 0; pxn < 2; pxn++) {
                int tin = (ly + pxn * 8) * 16 + lx;
                float aCr = 0.0f, aCg = 0.0f, aCb = 0.0f, aT = 1.0f;
                #pragma unroll
                for (int s = 0; s < N_SEG; s++) {
                    float4 p = __ldcg(basep + s * 256 + tin);
                    aCr = fmaf(aT, p.x, aCr);
                    aCg = fmaf(aT, p.y, aCg);
                    aCb = fmaf(aT, p.z, aCb);
                    aT *= p.w;
                }
                int x = tx*16 + lx, y = ty*16 + ly + pxn*8;
                int ppos = y * IMG_W + x;
                out[ppos]                 = aCr;
                out[IMG_H*IMG_W + ppos]   = aCg;
                out[2*IMG_H*IMG_W + ppos] = aCb;
            }

            // row completion: 8th tile of this row resets the row's list counters
            if (t == 0) {
                int rc = atomicAddAcqRelGpu(&g_rcnt[ty], 1);
                if (rc == N_ROW - 1) {
                    #pragma unroll
                    for (int s = 0; s < N_SEG; s++) g_bcnt[ty * N_SEG + s] = 0;
                    g_rcnt[ty] = 0;
                }
            }
        }
    }
}

// ---------------- launch ----------------
extern "C" void kernel_launch(void* const* d_in, const int* in_sizes, int n_in,
                              void* d_out, int out_size)
{
    const float* Ks     = (const float*)d_in[0];
    const float* vm     = (const float*)d_in[1];
    const float* means  = (const float*)d_in[2];
    const float* quats  = (const float*)d_in[3];
    const float* scales = (const float*)d_in[4];
    const float* ops    = (const float*)d_in[5];
    const float* rgb    = (const float*)d_in[6];
    float* out = (float*)d_out;

    mega_kernel<<<GRID, BLK>>>(Ks, vm, means, quats, scales, ops, rgb, out);
}